// round 6
// baseline (speedup 1.0000x reference)
#include <cuda_runtime.h>
#include <cuda_bf16.h>

#define DFEAT 128
#define MAX_NODES 100000
#define MAX_EDGES 650000
#define SCAN_BLK 1024

// scratch (static __device__ arrays — no allocations allowed)
__device__ int    g_is64;
__device__ int    g_deg[MAX_NODES];
__device__ int    g_off[MAX_NODES];
__device__ int    g_cur[MAX_NODES];
__device__ int    g_bsum[128];
__device__ float  g_dinv[MAX_NODES];
__device__ int    g_adj[2 * MAX_EDGES];
__device__ float4 g_tmp4[(size_t)MAX_NODES * (DFEAT / 4)];
__device__ __align__(16) __nv_bfloat16 g_Whi[128 * 128];
__device__ __align__(16) __nv_bfloat16 g_Wlo[128 * 128];

// ---------------------------------------------------------------------------
// Kernel 0: detect edge_index dtype (warp-parallel).
// int64 little-endian node ids (< 2^31) have zero high words at odd positions.
// ---------------------------------------------------------------------------
__global__ void k_detect(const int* __restrict__ ei_w) {
    int lane = threadIdx.x & 31;
    int z = 0;
    if (ei_w[2 * lane + 1] == 0) z++;
    if (ei_w[2 * (lane + 32) + 1] == 0) z++;
#pragma unroll
    for (int o = 16; o > 0; o >>= 1)
        z += __shfl_down_sync(0xffffffffu, z, o);
    if (lane == 0) g_is64 = (z >= 60) ? 1 : 0;
}

// ---------------------------------------------------------------------------
// Kernel 1: zero degree counters
// ---------------------------------------------------------------------------
__global__ void k_zero(int n) {
    int i = blockIdx.x * blockDim.x + threadIdx.x;
    if (i < n) g_deg[i] = 0;
}

// ---------------------------------------------------------------------------
// Kernel 2: degree histogram (both endpoints)
// ---------------------------------------------------------------------------
__global__ void k_deg(const int* __restrict__ ei_w, int E) {
    int i = blockIdx.x * blockDim.x + threadIdx.x;
    if (i < E) {
        int stride = g_is64 ? 2 : 1;
        int s = ei_w[(size_t)i * stride];
        int d = ei_w[(size_t)(E + i) * stride];
        atomicAdd(&g_deg[s], 1);
        atomicAdd(&g_deg[d], 1);
    }
}

// ---------------------------------------------------------------------------
// Kernel 3a: per-block exclusive scan (shuffle-based, 2 barriers) + fused dinv
// ---------------------------------------------------------------------------
__global__ void k_scan1(int n) {
    __shared__ int ws[32];
    int tid  = threadIdx.x;
    int lane = tid & 31, wid = tid >> 5;
    int i = blockIdx.x * SCAN_BLK + tid;
    int v = (i < n) ? g_deg[i] : 0;

    int s = v;
#pragma unroll
    for (int o = 1; o < 32; o <<= 1) {
        int t = __shfl_up_sync(0xffffffffu, s, o);
        if (lane >= o) s += t;
    }
    if (lane == 31) ws[wid] = s;
    __syncthreads();
    if (wid == 0) {
        int t = ws[lane];
        int ss = t;
#pragma unroll
        for (int o = 1; o < 32; o <<= 1) {
            int u = __shfl_up_sync(0xffffffffu, ss, o);
            if (lane >= o) ss += u;
        }
        ws[lane] = ss - t;  // exclusive warp offsets
    }
    __syncthreads();
    int excl = ws[wid] + s - v;
    if (i < n) {
        g_off[i]  = excl;
        g_dinv[i] = (v > 0) ? rsqrtf((float)v) : 0.0f;
    }
    if (tid == SCAN_BLK - 1) g_bsum[blockIdx.x] = excl + v;
}

// ---------------------------------------------------------------------------
// Kernel 3b: exclusive scan of block sums (single block, nb <= 128)
// ---------------------------------------------------------------------------
__global__ void k_scan2(int nb) {
    __shared__ int sm[128];
    int tid = threadIdx.x;
    int v = (tid < nb) ? g_bsum[tid] : 0;
    sm[tid] = v;
    __syncthreads();
#pragma unroll
    for (int off = 1; off < 128; off <<= 1) {
        int t = (tid >= off) ? sm[tid - off] : 0;
        __syncthreads();
        sm[tid] += t;
        __syncthreads();
    }
    if (tid < nb) g_bsum[tid] = sm[tid] - v;
}

// ---------------------------------------------------------------------------
// Kernel 3c: add block offsets, init scatter cursors
// ---------------------------------------------------------------------------
__global__ void k_scan3(int n) {
    int i = blockIdx.x * blockDim.x + threadIdx.x;
    if (i < n) {
        int o = g_off[i] + g_bsum[i >> 10];
        g_off[i] = o;
        g_cur[i] = o;
    }
}

// ---------------------------------------------------------------------------
// Kernel 4: scatter neighbor ids into CSR adjacency
// ---------------------------------------------------------------------------
__global__ void k_scatter(const int* __restrict__ ei_w, int E) {
    int i = blockIdx.x * blockDim.x + threadIdx.x;
    if (i < E) {
        int stride = g_is64 ? 2 : 1;
        int s = ei_w[(size_t)i * stride];
        int d = ei_w[(size_t)(E + i) * stride];
        int ps = atomicAdd(&g_cur[s], 1);
        g_adj[ps] = d;
        int pd = atomicAdd(&g_cur[d], 1);
        g_adj[pd] = s;
    }
}

// ---------------------------------------------------------------------------
// Kernel 5: gather aggregation, warp per node, 4-edge unroll (MLP=4).
// h[v] = x[v] + dinv[v] * sum_nb dinv[nb] * x[nb]
// ---------------------------------------------------------------------------
__global__ void k_gather(const float4* __restrict__ x4, int n) {
    int v    = (blockIdx.x * blockDim.x + threadIdx.x) >> 5;
    int lane = threadIdx.x & 31;
    if (v >= n) return;

    int base = g_off[v];
    int deg  = g_deg[v];

    float4 acc = make_float4(0.f, 0.f, 0.f, 0.f);
    int e = 0;
    int deg4 = deg & ~3;
    for (; e < deg4; e += 4) {
        int nb0 = __ldg(&g_adj[base + e]);
        int nb1 = __ldg(&g_adj[base + e + 1]);
        int nb2 = __ldg(&g_adj[base + e + 2]);
        int nb3 = __ldg(&g_adj[base + e + 3]);
        float w0 = __ldg(&g_dinv[nb0]);
        float w1 = __ldg(&g_dinv[nb1]);
        float w2 = __ldg(&g_dinv[nb2]);
        float w3 = __ldg(&g_dinv[nb3]);
        float4 v0 = __ldg(x4 + (size_t)nb0 * 32 + lane);
        float4 v1 = __ldg(x4 + (size_t)nb1 * 32 + lane);
        float4 v2 = __ldg(x4 + (size_t)nb2 * 32 + lane);
        float4 v3 = __ldg(x4 + (size_t)nb3 * 32 + lane);
        acc.x += w0 * v0.x + w1 * v1.x + w2 * v2.x + w3 * v3.x;
        acc.y += w0 * v0.y + w1 * v1.y + w2 * v2.y + w3 * v3.y;
        acc.z += w0 * v0.z + w1 * v1.z + w2 * v2.z + w3 * v3.z;
        acc.w += w0 * v0.w + w1 * v1.w + w2 * v2.w + w3 * v3.w;
    }
    for (; e < deg; e++) {
        int nb = __ldg(&g_adj[base + e]);
        float w = __ldg(&g_dinv[nb]);
        float4 vv = __ldg(x4 + (size_t)nb * 32 + lane);
        acc.x += w * vv.x; acc.y += w * vv.y;
        acc.z += w * vv.z; acc.w += w * vv.w;
    }

    float dv = g_dinv[v];
    float4 xv = __ldg(x4 + (size_t)v * 32 + lane);
    float4 h;
    h.x = xv.x + dv * acc.x;
    h.y = xv.y + dv * acc.y;
    h.z = xv.z + dv * acc.z;
    h.w = xv.w + dv * acc.w;
    g_tmp4[(size_t)v * 32 + lane] = h;
}

// ---------------------------------------------------------------------------
// Kernel 6: split W into bf16 hi/lo (once per launch; W is tiny)
// ---------------------------------------------------------------------------
__global__ void k_wsplit(const float* __restrict__ W) {
    int i = blockIdx.x * blockDim.x + threadIdx.x;
    if (i < 128 * 128) {
        float v = W[i];
        __nv_bfloat16 h = __float2bfloat16(v);
        g_Whi[i] = h;
        g_Wlo[i] = __float2bfloat16(v - __bfloat162float(h));
    }
}

// ---------------------------------------------------------------------------
// Kernel 7: out = relu(h @ W^T + b) via split-bf16 tensor-core MMA.
// Block: 256 threads (8 warps: 4 in M x 2 in N), tile M=128, N=128.
// 3-pass Ootomo split: acc += Ahi*Bhi + Ahi*Blo + Alo*Bhi  (error ~2^-18).
// K streamed in 4 chunks of 32 through smem.
// ---------------------------------------------------------------------------
#define ASTRIDE 36   // bf16 elements per smem row (32 + 4 pad)

__device__ __forceinline__ void mma_bf16(float c[4], unsigned a0, unsigned a1,
                                         unsigned a2, unsigned a3,
                                         unsigned b0, unsigned b1) {
    asm volatile(
        "mma.sync.aligned.m16n8k16.row.col.f32.bf16.bf16.f32 "
        "{%0,%1,%2,%3}, {%4,%5,%6,%7}, {%8,%9}, {%0,%1,%2,%3};\n"
        : "+f"(c[0]), "+f"(c[1]), "+f"(c[2]), "+f"(c[3])
        : "r"(a0), "r"(a1), "r"(a2), "r"(a3), "r"(b0), "r"(b1));
}

__global__ __launch_bounds__(256, 1)
void k_gemm_relu(const float* __restrict__ b,
                 float* __restrict__ out, int n) {
    __shared__ __nv_bfloat16 Ahi[128 * ASTRIDE];
    __shared__ __nv_bfloat16 Alo[128 * ASTRIDE];
    __shared__ __nv_bfloat16 Bhi[128 * ASTRIDE];
    __shared__ __nv_bfloat16 Blo[128 * ASTRIDE];

    int tid  = threadIdx.x;
    int lane = tid & 31;
    int warp = tid >> 5;
    int wm   = warp >> 1;       // 0..3 (M direction, 32 rows each)
    int wn   = warp & 1;        // 0..1 (N direction, 64 cols each)
    int g    = lane >> 2;       // 0..7
    int q    = lane & 3;        // 0..3
    int row0 = blockIdx.x * 128;

    float acc[2][8][4];
#pragma unroll
    for (int mt = 0; mt < 2; mt++)
#pragma unroll
        for (int nt = 0; nt < 8; nt++)
#pragma unroll
            for (int c = 0; c < 4; c++) acc[mt][nt][c] = 0.0f;

    for (int kc = 0; kc < 4; kc++) {
        __syncthreads();
        // Load h chunk [128 rows x 32 k] fp32, split into bf16 hi/lo.
        for (int i = tid; i < 1024; i += 256) {
            int r = i >> 3, f = i & 7;       // f4 index within chunk
            float4 v = make_float4(0.f, 0.f, 0.f, 0.f);
            if (row0 + r < n) v = g_tmp4[(size_t)(row0 + r) * 32 + kc * 8 + f];
            int kk = f * 4;
            __nv_bfloat162 h01 = __floats2bfloat162_rn(v.x, v.y);
            __nv_bfloat162 h23 = __floats2bfloat162_rn(v.z, v.w);
            __nv_bfloat162 l01 = __floats2bfloat162_rn(
                v.x - __bfloat162float(h01.x), v.y - __bfloat162float(h01.y));
            __nv_bfloat162 l23 = __floats2bfloat162_rn(
                v.z - __bfloat162float(h23.x), v.w - __bfloat162float(h23.y));
            *(__nv_bfloat162*)&Ahi[r * ASTRIDE + kk]     = h01;
            *(__nv_bfloat162*)&Ahi[r * ASTRIDE + kk + 2] = h23;
            *(__nv_bfloat162*)&Alo[r * ASTRIDE + kk]     = l01;
            *(__nv_bfloat162*)&Alo[r * ASTRIDE + kk + 2] = l23;
        }
        // Load W chunk [128 n x 32 k] bf16 hi/lo (pre-split).
        for (int i = tid; i < 2048; i += 256) {
            int r = i >> 4, u = i & 15;      // u: uint (2 bf16) within chunk
            ((unsigned*)Bhi)[r * (ASTRIDE / 2) + u] =
                ((const unsigned*)g_Whi)[r * 64 + kc * 16 + u];
            ((unsigned*)Blo)[r * (ASTRIDE / 2) + u] =
                ((const unsigned*)g_Wlo)[r * 64 + kc * 16 + u];
        }
        __syncthreads();

#pragma unroll
        for (int ks = 0; ks < 2; ks++) {
            int kk = ks * 16 + 2 * q;
            unsigned ahi[2][4], alo[2][4];
#pragma unroll
            for (int mt = 0; mt < 2; mt++) {
                int row = wm * 32 + mt * 16 + g;
                ahi[mt][0] = *(const unsigned*)&Ahi[row * ASTRIDE + kk];
                ahi[mt][1] = *(const unsigned*)&Ahi[(row + 8) * ASTRIDE + kk];
                ahi[mt][2] = *(const unsigned*)&Ahi[row * ASTRIDE + kk + 8];
                ahi[mt][3] = *(const unsigned*)&Ahi[(row + 8) * ASTRIDE + kk + 8];
                alo[mt][0] = *(const unsigned*)&Alo[row * ASTRIDE + kk];
                alo[mt][1] = *(const unsigned*)&Alo[(row + 8) * ASTRIDE + kk];
                alo[mt][2] = *(const unsigned*)&Alo[row * ASTRIDE + kk + 8];
                alo[mt][3] = *(const unsigned*)&Alo[(row + 8) * ASTRIDE + kk + 8];
            }
#pragma unroll
            for (int nt = 0; nt < 8; nt++) {
                int nr = wn * 64 + nt * 8 + g;
                unsigned bh0 = *(const unsigned*)&Bhi[nr * ASTRIDE + kk];
                unsigned bh1 = *(const unsigned*)&Bhi[nr * ASTRIDE + kk + 8];
                unsigned bl0 = *(const unsigned*)&Blo[nr * ASTRIDE + kk];
                unsigned bl1 = *(const unsigned*)&Blo[nr * ASTRIDE + kk + 8];
#pragma unroll
                for (int mt = 0; mt < 2; mt++) {
                    mma_bf16(acc[mt][nt], ahi[mt][0], ahi[mt][1], ahi[mt][2], ahi[mt][3], bh0, bh1);
                    mma_bf16(acc[mt][nt], ahi[mt][0], ahi[mt][1], ahi[mt][2], ahi[mt][3], bl0, bl1);
                    mma_bf16(acc[mt][nt], alo[mt][0], alo[mt][1], alo[mt][2], alo[mt][3], bh0, bh1);
                }
            }
        }
    }

    // Epilogue: bias + relu, float2 stores.
#pragma unroll
    for (int mt = 0; mt < 2; mt++) {
#pragma unroll
        for (int nt = 0; nt < 8; nt++) {
            int gcol = wn * 64 + nt * 8 + 2 * q;
            float2 bv = *(const float2*)&b[gcol];
            int r0 = row0 + wm * 32 + mt * 16 + g;
            if (r0 < n) {
                float2 o;
                o.x = fmaxf(acc[mt][nt][0] + bv.x, 0.0f);
                o.y = fmaxf(acc[mt][nt][1] + bv.y, 0.0f);
                *(float2*)&out[(size_t)r0 * DFEAT + gcol] = o;
            }
            int r1 = r0 + 8;
            if (r1 < n) {
                float2 o;
                o.x = fmaxf(acc[mt][nt][2] + bv.x, 0.0f);
                o.y = fmaxf(acc[mt][nt][3] + bv.y, 0.0f);
                *(float2*)&out[(size_t)r1 * DFEAT + gcol] = o;
            }
        }
    }
}

// ---------------------------------------------------------------------------
// kernel_launch
// inputs: 0=x [N,128] f32, 1=edge_index [2,E] int32/int64, 2=W [128,128], 3=b [128]
// ---------------------------------------------------------------------------
extern "C" void kernel_launch(void* const* d_in, const int* in_sizes, int n_in,
                              void* d_out, int out_size) {
    const float* x    = (const float*)d_in[0];
    const int*   ei_w = (const int*)d_in[1];
    const float* W    = (const float*)d_in[2];
    const float* b    = (const float*)d_in[3];
    float*       out  = (float*)d_out;

    int n = in_sizes[0] / DFEAT;
    int E = in_sizes[1] / 2;
    int nb = (n + SCAN_BLK - 1) / SCAN_BLK;

    k_detect<<<1, 32>>>(ei_w);
    k_zero<<<(n + 1023) / 1024, 1024>>>(n);
    k_wsplit<<<64, 256>>>(W);
    k_deg<<<(E + 255) / 256, 256>>>(ei_w, E);
    k_scan1<<<nb, SCAN_BLK>>>(n);
    k_scan2<<<1, 128>>>(nb);
    k_scan3<<<(n + 255) / 256, 256>>>(n);
    k_scatter<<<(E + 255) / 256, 256>>>(ei_w, E);
    {
        long long tthreads = (long long)n * 32;
        int blocks = (int)((tthreads + 255) / 256);
        k_gather<<<blocks, 256>>>((const float4*)x, n);
    }
    k_gemm_relu<<<(n + 127) / 128, 256>>>(b, out, n);
}